// round 12
// baseline (speedup 1.0000x reference)
#include <cuda_runtime.h>
#include <cuda_fp16.h>
#include <math.h>

#define NN 40000
#define EE 600000
#define HC 128          // H*C
#define FUSED 384

// phase1 grid: exactly-resident persistent blocks (2/SM x 148), 256 threads
#define NB_C0 110
#define NB_C1 110
#define NB_C2 56
#define NB_SC 20
#define NB_TOT (NB_C0 + NB_C1 + NB_C2 + NB_SC)   // 296
#define P1_SMEM 98304                            // 64KB Bs + 32KB As

typedef unsigned long long u64;

// ---------------- scratch (device globals; no allocation allowed) -------------
__device__ __align__(16) __half g_xw[3][NN * HC];  // transformed features (fp16)
__device__ __align__(8)  float g_as[3][NN * 2];    // a_src per node/head
__device__ __align__(8)  float g_ad[3][NN * 2];    // a_dst per node/head
__device__ int        g_deg[3][NN];
__device__ int        g_rowptr[3][NN + 1];
__device__ int        g_cur[3][NN];
__device__ int        g_srt[3][EE];                // src ids sorted by dst
__device__ ulonglong2 g_Wc1q[12288];               // quad-packed Wc1

__device__ __forceinline__ void ffma2(u64& acc, u64 a, u64 b)
{
    asm("fma.rn.f32x2 %0, %1, %2, %0;" : "+l"(acc) : "l"(a), "l"(b));
}
__device__ __forceinline__ void unpack2(float& lo, float& hi, u64 v)
{
    asm("mov.b64 {%0,%1}, %2;" : "=f"(lo), "=f"(hi) : "l"(v));
}
__device__ __forceinline__ float unpack_sum(u64 v)
{
    float lo, hi; unpack2(lo, hi, v); return lo + hi;
}
__device__ __forceinline__ u64 packf2(float lo, float hi)
{
    u64 r; asm("mov.b64 %0, {%1,%2};" : "=l"(r) : "f"(lo), "f"(hi)); return r;
}

// ---------------- k0: Wc1 pre-pack ---------------------------------------------
__global__ void __launch_bounds__(256)
pack_kernel(const float* __restrict__ Wc1)
{
    const int i = blockIdx.x * 256 + threadIdx.x;
    if (i >= 12288) return;
    const int c = i & 127, k4 = i >> 7;
    const float v0 = Wc1[(4 * k4 + 0) * 128 + c];
    const float v1 = Wc1[(4 * k4 + 1) * 128 + c];
    const float v2 = Wc1[(4 * k4 + 2) * 128 + c];
    const float v3 = Wc1[(4 * k4 + 3) * 128 + c];
    ulonglong2 q; q.x = packf2(v0, v1); q.y = packf2(v2, v3);
    g_Wc1q[i] = q;
}

// ---------------- k1: degree histogram -----------------------------------------
__global__ void __launch_bounds__(256)
hist_kernel(const int* __restrict__ e0, const int* __restrict__ e1,
            const int* __restrict__ e2)
{
    const int g = blockIdx.x * 256 + threadIdx.x;
    if (g >= 3 * EE) return;
    const int cat = g / EE, le = g - cat * EE;
    const int* ei = cat == 0 ? e0 : (cat == 1 ? e1 : e2);
    atomicAdd(&g_deg[cat][ei[EE + le]], 1);
}

// ---------------- k2: CSR scan -------------------------------------------------
__global__ void scan3_kernel()
{
    const int cat = blockIdx.x;
    const int* deg = g_deg[cat];
    int* rowptr = g_rowptr[cat];
    int* cur = g_cur[cat];
    const int t = threadIdx.x;              // 0..1023
    const int CH = (NN + 1023) / 1024;      // 40
    const int lo = t * CH;
    const int hi = min(lo + CH, NN);
    int s = 0;
    for (int i = lo; i < hi; i++) s += deg[i];
    __shared__ int wsum[32];
    const int lane = t & 31, wid = t >> 5;
    int v = s;
#pragma unroll
    for (int o = 1; o < 32; o <<= 1) {
        const int u = __shfl_up_sync(0xFFFFFFFFu, v, o);
        if (lane >= o) v += u;
    }
    if (lane == 31) wsum[wid] = v;
    __syncthreads();
    if (wid == 0) {
        int u = wsum[lane];
#pragma unroll
        for (int o = 1; o < 32; o <<= 1) {
            const int t2 = __shfl_up_sync(0xFFFFFFFFu, u, o);
            if (lane >= o) u += t2;
        }
        wsum[lane] = u;
    }
    __syncthreads();
    int run = v - s + (wid ? wsum[wid - 1] : 0);
    for (int i = lo; i < hi; i++) {
        rowptr[i] = run; cur[i] = run; run += deg[i];
    }
    if (t == 1023) rowptr[NN] = run;
}

// ------- outer-product GEMM body (64 rows x 128 cols per tile, 256 thr) -------
template <int DIN>
__device__ __forceinline__ void gemm_body(const float* __restrict__ x,
                                          const float* __restrict__ W,
                                          const float* __restrict__ att_s,
                                          const float* __restrict__ att_d,
                                          __half* __restrict__ xw,
                                          float* __restrict__ as_,
                                          float* __restrict__ ad_,
                                          int bid, int nb, float* sm)
{
    float* Bs = sm;                    // [DIN][128]
    float* As = sm + DIN * 128;        // [64][DIN] row-major
    const int tid = threadIdx.x, wid = tid >> 5, lane = tid & 31;

    // load weights once per block (coalesced, conflict-free)
    for (int i = tid; i < DIN * 32; i += 256)
        reinterpret_cast<float4*>(Bs)[i] = reinterpret_cast<const float4*>(W)[i];
    const float4 s4 = __ldg(reinterpret_cast<const float4*>(att_s) + lane);
    const float4 d4 = __ldg(reinterpret_cast<const float4*>(att_d) + lane);
    __syncthreads();

    for (int g = bid; g < NN / 64; g += nb) {
        const int n0 = g * 64;
        for (int i = tid; i < 16 * DIN; i += 256)
            reinterpret_cast<float4*>(As)[i] =
                reinterpret_cast<const float4*>(x + (size_t)n0 * DIN)[i];
        __syncthreads();

        u64 acc2[8][2];
#pragma unroll
        for (int r = 0; r < 8; r++) { acc2[r][0] = 0ull; acc2[r][1] = 0ull; }

        const float4* As4 = reinterpret_cast<const float4*>(As) +
                            (wid * 8) * (DIN / 4);
        const float4* Bs4 = reinterpret_cast<const float4*>(Bs);
#pragma unroll 2
        for (int k4 = 0; k4 < DIN / 4; k4++) {
            float4 a4[8];
#pragma unroll
            for (int r = 0; r < 8; r++) a4[r] = As4[r * (DIN / 4) + k4];
#pragma unroll
            for (int kk = 0; kk < 4; kk++) {
                const float4 b4 = Bs4[(4 * k4 + kk) * 32 + lane];
                const u64 b01 = packf2(b4.x, b4.y);
                const u64 b23 = packf2(b4.z, b4.w);
#pragma unroll
                for (int r = 0; r < 8; r++) {
                    const float av = kk == 0 ? a4[r].x : kk == 1 ? a4[r].y :
                                     kk == 2 ? a4[r].z : a4[r].w;
                    const u64 aa = packf2(av, av);
                    ffma2(acc2[r][0], aa, b01);
                    ffma2(acc2[r][1], aa, b23);
                }
            }
        }

        // epilogue: fp16 store + per-head attention dots (warp owns its 8 rows)
#pragma unroll
        for (int r = 0; r < 8; r++) {
            const int row = n0 + wid * 8 + r;
            float x0, x1, x2, x3;
            unpack2(x0, x1, acc2[r][0]);
            unpack2(x2, x3, acc2[r][1]);
            const __half2 h01 = __floats2half2_rn(x0, x1);
            const __half2 h23 = __floats2half2_rn(x2, x3);
            uint2 hv;
            hv.x = *reinterpret_cast<const unsigned*>(&h01);
            hv.y = *reinterpret_cast<const unsigned*>(&h23);
            *(reinterpret_cast<uint2*>(xw + (size_t)row * HC) + lane) = hv;
            float ps = x0 * s4.x + x1 * s4.y + x2 * s4.z + x3 * s4.w;
            float pd = x0 * d4.x + x1 * d4.y + x2 * d4.z + x3 * d4.w;
#pragma unroll
            for (int o = 8; o; o >>= 1) {      // segmented: stays within 16-group
                ps += __shfl_xor_sync(0xFFFFFFFFu, ps, o);
                pd += __shfl_xor_sync(0xFFFFFFFFu, pd, o);
            }
            if ((lane & 15) == 0) {            // lane0 -> head0, lane16 -> head1
                as_[row * 2 + (lane >> 4)] = ps;
                ad_[row * 2 + (lane >> 4)] = pd;
            }
        }
        __syncthreads();
    }
}

// ---------------- k3: 3 outer-product GEMMs + pipelined scatter ---------------
__global__ void __launch_bounds__(256)
phase1_kernel(const float* __restrict__ x0, const float* __restrict__ x1,
              const float* __restrict__ x2,
              const float* __restrict__ W0, const float* __restrict__ W1,
              const float* __restrict__ W2,
              const float* __restrict__ s0, const float* __restrict__ s1,
              const float* __restrict__ s2,
              const float* __restrict__ t0, const float* __restrict__ t1,
              const float* __restrict__ t2,
              const int* __restrict__ e0, const int* __restrict__ e1,
              const int* __restrict__ e2)
{
    extern __shared__ float sm[];
    const int b = blockIdx.x;
    if (b < NB_C0)
        gemm_body<128>(x0, W0, s0, t0, g_xw[0], g_as[0], g_ad[0],
                       b, NB_C0, sm);
    else if (b < NB_C0 + NB_C1)
        gemm_body<128>(x1, W1, s1, t1, g_xw[1], g_as[1], g_ad[1],
                       b - NB_C0, NB_C1, sm);
    else if (b < NB_C0 + NB_C1 + NB_C2)
        gemm_body<64>(x2, W2, s2, t2, g_xw[2], g_as[2], g_ad[2],
                      b - NB_C0 - NB_C1, NB_C2, sm);
    else {
        // scatter role: batch-8 pipelined CSR scatter (hidden under GEMM)
        const int t = (b - NB_C0 - NB_C1 - NB_C2) * 256 + threadIdx.x;
        const int NT = NB_SC * 256;
        for (int base = 0; base < 3 * EE; base += NT * 8) {
            int src[8], dst[8], cat[8];
            bool ok[8];
#pragma unroll
            for (int j = 0; j < 8; j++) {
                const int e = base + j * NT + t;
                ok[j] = e < 3 * EE;
                if (ok[j]) {
                    cat[j] = e >= 2 * EE ? 2 : (e >= EE ? 1 : 0);
                    const int le = e - cat[j] * EE;
                    const int* ei = cat[j] == 0 ? e0 : (cat[j] == 1 ? e1 : e2);
                    src[j] = __ldg(ei + le);
                    dst[j] = __ldg(ei + EE + le);
                }
            }
#pragma unroll
            for (int j = 0; j < 8; j++) {
                if (ok[j]) {
                    const int pos = atomicAdd(&g_cur[cat[j]][dst[j]], 1);
                    g_srt[cat[j]][pos] = src[j];
                }
            }
        }
    }
}

// ---------------- k4: fused gather + softmax + ELU + MLP (16 nodes/block) -----
__global__ void __launch_bounds__(256)
gather_mlp_kernel(const float* __restrict__ b0, const float* __restrict__ b1,
                  const float* __restrict__ b2,
                  const float* __restrict__ bc1, const float* __restrict__ Wc2,
                  const float* __restrict__ bc2, float* __restrict__ out)
{
    __shared__ __align__(16) float hs[16 * FUSED];
    __shared__ __align__(16) int4 recs[8][32];     // per-warp edge-record stage
    __shared__ float redm[8][8];
    const int tid = threadIdx.x, wid = tid >> 5, lane = tid & 31;
    const int n0 = blockIdx.x * 16;
    const int h = lane >> 4;                  // lanes 0-15 head0, 16-31 head1

    // -------- gather: each warp processes rows wid and wid+8 ------------------
    for (int cat = 0; cat < 3; cat++) {
        const float*  as_ = g_as[cat];
        const __half* xw  = g_xw[cat];
        const int*    srt = g_srt[cat];
        const float*  bias = cat == 0 ? b0 : (cat == 1 ? b1 : b2);

#pragma unroll
        for (int rep = 0; rep < 2; rep++) {
            const int row = wid + rep * 8;
            const int dst = n0 + row;

            const float2 ad2 = *reinterpret_cast<const float2*>(&g_ad[cat][dst * 2]);
            const float2 as2 = __ldg(reinterpret_cast<const float2*>(as_) + dst);
            float t0 = as2.x + ad2.x; t0 = t0 > 0.f ? t0 : 0.2f * t0;
            float t1 = as2.y + ad2.y; t1 = t1 > 0.f ? t1 : 0.2f * t1;
            const float exs0 = __expf(t0), exs1 = __expf(t1);
            float d0 = (lane == 0) ? exs0 : 0.f;
            float d1 = (lane == 0) ? exs1 : 0.f;
            const float exself = h ? exs1 : exs0;
            const uint2 sv = __ldg(reinterpret_cast<const uint2*>(
                                       xw + (size_t)dst * HC) + lane);
            float2 sa = __half22float2(*reinterpret_cast<const __half2*>(&sv.x));
            float2 sb = __half22float2(*reinterpret_cast<const __half2*>(&sv.y));
            float4 acc = make_float4(sa.x * exself, sa.y * exself,
                                     sb.x * exself, sb.y * exself);

            const int start = __ldg(&g_rowptr[cat][dst]);
            const int end   = __ldg(&g_rowptr[cat][dst + 1]);
            for (int p = start; p < end; p += 32) {
                const int n = min(32, end - p);
                const int mysrc = (lane < n) ? __ldg(srt + p + lane) : 0;
                const float2 a = __ldg(reinterpret_cast<const float2*>(as_) + mysrc);
                float u0 = a.x + ad2.x; u0 = u0 > 0.f ? u0 : 0.2f * u0;
                float u1 = a.y + ad2.y; u1 = u1 > 0.f ? u1 : 0.2f * u1;
                const float x0 = __expf(u0), x1 = __expf(u1);
                if (lane < n) { d0 += x0; d1 += x1; }
                recs[wid][lane] = make_int4(mysrc, __float_as_int(x0),
                                            __float_as_int(x1), 0);
                __syncwarp();
#pragma unroll 4
                for (int i = 0; i < n; i++) {
                    const int4 rec = recs[wid][i];     // broadcast LDS
                    const float exh = h ? __int_as_float(rec.z)
                                        : __int_as_float(rec.y);
                    const uint2 uv = __ldg(reinterpret_cast<const uint2*>(
                                               xw + (size_t)rec.x * HC) + lane);
                    float2 fa = __half22float2(
                        *reinterpret_cast<const __half2*>(&uv.x));
                    float2 fb = __half22float2(
                        *reinterpret_cast<const __half2*>(&uv.y));
                    acc.x += fa.x * exh; acc.y += fa.y * exh;
                    acc.z += fb.x * exh; acc.w += fb.y * exh;
                }
                __syncwarp();
            }
#pragma unroll
            for (int o = 16; o; o >>= 1) {
                d0 += __shfl_xor_sync(0xFFFFFFFFu, d0, o);
                d1 += __shfl_xor_sync(0xFFFFFFFFu, d1, o);
            }
            const float inv = __fdividef(1.f, h ? d1 : d0);
            const int col = lane * 4;
            float4 o;
            o.x = acc.x * inv + bias[col + 0]; o.x = o.x > 0.f ? o.x : expm1f(o.x);
            o.y = acc.y * inv + bias[col + 1]; o.y = o.y > 0.f ? o.y : expm1f(o.y);
            o.z = acc.z * inv + bias[col + 2]; o.z = o.z > 0.f ? o.z : expm1f(o.z);
            o.w = acc.w * inv + bias[col + 3]; o.w = o.w > 0.f ? o.w : expm1f(o.w);
            *reinterpret_cast<float4*>(&hs[row * FUSED + cat * HC + col]) = o;
        }
    }
    __syncthreads();

    // ---- MLP: two 128-thread groups, each full-K over its own 8 rows ---------
    const int j = tid & 127;           // hidden unit
    const int grp = tid >> 7;          // 0 -> rows 0-7, 1 -> rows 8-15
    u64 acc2[8];
#pragma unroll
    for (int r = 0; r < 8; r++) acc2[r] = 0ull;
#pragma unroll 2
    for (int k4 = 0; k4 < FUSED / 4; k4++) {
        const ulonglong2 wp = g_Wc1q[k4 * 128 + j];
#pragma unroll
        for (int r = 0; r < 8; r++) {
            const ulonglong2 a = *reinterpret_cast<const ulonglong2*>(
                &hs[(grp * 8 + r) * FUSED + 4 * k4]);
            ffma2(acc2[r], a.x, wp.x);
            ffma2(acc2[r], a.y, wp.y);
        }
    }
    const float w2c = Wc2[j];
    const float b1c = bc1[j];
#pragma unroll
    for (int r = 0; r < 8; r++) {
        float hv = unpack_sum(acc2[r]) + b1c;
        hv = fmaxf(hv, 0.f);
        float p = hv * w2c;
#pragma unroll
        for (int o = 16; o; o >>= 1) p += __shfl_down_sync(0xFFFFFFFFu, p, o);
        if (lane == 0) redm[wid][r] = p;   // wid 0-3: rows 0-7; wid 4-7: rows 8-15
    }
    __syncthreads();
    if (tid < 16) {
        const int grp2 = tid >> 3;         // which group owns this row
        const int r = tid & 7;
        const int wbase = grp2 * 4;
        out[n0 + tid] = redm[wbase + 0][r] + redm[wbase + 1][r] +
                        redm[wbase + 2][r] + redm[wbase + 3][r] + bc2[0];
    }
}

// ---------------- host orchestration ------------------------------------------
extern "C" void kernel_launch(void* const* d_in, const int* in_sizes, int n_in,
                              void* d_out, int out_size)
{
    const float* x[3];  const int* ei[3];  const float* W[3];
    const float* atts[3]; const float* attd[3]; const float* bias[3];
    for (int i = 0; i < 3; i++) {
        x[i]    = (const float*)d_in[6 * i + 0];
        ei[i]   = (const int*)  d_in[6 * i + 1];
        W[i]    = (const float*)d_in[6 * i + 2];
        atts[i] = (const float*)d_in[6 * i + 3];
        attd[i] = (const float*)d_in[6 * i + 4];
        bias[i] = (const float*)d_in[6 * i + 5];
    }
    const float* Wc1 = (const float*)d_in[18];
    const float* bc1 = (const float*)d_in[19];
    const float* Wc2 = (const float*)d_in[20];
    const float* bc2 = (const float*)d_in[21];
    float* out = (float*)d_out;

    cudaFuncSetAttribute(phase1_kernel,
                         cudaFuncAttributeMaxDynamicSharedMemorySize, P1_SMEM);

    int* p_deg;
    cudaGetSymbolAddress((void**)&p_deg, g_deg);
    cudaMemsetAsync(p_deg, 0, sizeof(int) * 3 * NN);

    // k0: pack Wc1   k1: hist   k2: scan   k3: phase1 (capture slot)   k4: gather
    pack_kernel<<<48, 256>>>(Wc1);

    hist_kernel<<<(3 * EE + 255) / 256, 256>>>(ei[0], ei[1], ei[2]);

    scan3_kernel<<<3, 1024>>>();

    phase1_kernel<<<NB_TOT, 256, P1_SMEM>>>(
        x[0], x[1], x[2], W[0], W[1], W[2],
        atts[0], atts[1], atts[2],
        attd[0], attd[1], attd[2],
        ei[0], ei[1], ei[2]);

    gather_mlp_kernel<<<NN / 16, 256>>>(bias[0], bias[1], bias[2],
                                        bc1, Wc2, bc2, out);
}

// round 13
// speedup vs baseline: 1.1313x; 1.1313x over previous
#include <cuda_runtime.h>
#include <cuda_fp16.h>
#include <math.h>

#define NN 40000
#define EE 600000
#define HC 128          // H*C
#define FUSED 384
#define ROLES 11        // 4 cat0 + 4 cat1 + 2 cat2 + 1 scatter
#define RPB 431         // ranks per role
#define P1GRID (ROLES * RPB)

typedef unsigned long long u64;

// ---------------- scratch (device globals; no allocation allowed) -------------
__device__ __align__(16) __half g_xw[3][NN * HC];  // transformed features (fp16)
__device__ __align__(8)  float g_as[3][NN * 2];    // a_src per node/head
__device__ __align__(8)  float g_ad[3][NN * 2];    // a_dst per node/head
__device__ int        g_deg[3][NN];
__device__ int        g_rowptr[3][NN + 1];
__device__ int        g_cur[3][NN];
__device__ int        g_srt[3][EE];                // src ids sorted by dst
__device__ ulonglong2 g_Wq[3][4096];               // quad-packed W (fp32 k-quads)
__device__ ulonglong2 g_Wc1h[6144];                // fp16-packed Wc1 (8 k / 16B)

__device__ __forceinline__ void ffma2(u64& acc, u64 a, u64 b)
{
    asm("fma.rn.f32x2 %0, %1, %2, %0;" : "+l"(acc) : "l"(a), "l"(b));
}
__device__ __forceinline__ float unpack_sum(u64 v)
{
    float lo, hi;
    asm("mov.b64 {%0,%1}, %2;" : "=f"(lo), "=f"(hi) : "l"(v));
    return lo + hi;
}
__device__ __forceinline__ u64 packf2(float lo, float hi)
{
    u64 r; asm("mov.b64 %0, {%1,%2};" : "=l"(r) : "f"(lo), "f"(hi)); return r;
}
__device__ __forceinline__ u64 h2_to_u64f2(unsigned h2bits)
{
    const float2 f = __half22float2(*reinterpret_cast<const __half2*>(&h2bits));
    return packf2(f.x, f.y);
}

// ---------------- k0: weight pre-pack + degree histogram ----------------------
__global__ void __launch_bounds__(256)
pack_hist_kernel(const float* __restrict__ W0, const float* __restrict__ W1,
                 const float* __restrict__ W2, const float* __restrict__ Wc1,
                 const int* __restrict__ e0, const int* __restrict__ e1,
                 const int* __restrict__ e2)
{
    if (blockIdx.x < 64) {      // pack role
        const int i = blockIdx.x * 256 + threadIdx.x;
        if (i < 10240) {        // fp32 quad-pack of the three GAT weights
            const float* W; ulonglong2* dst; int base;
            if      (i <  4096) { W = W0; dst = g_Wq[0]; base = i; }
            else if (i <  8192) { W = W1; dst = g_Wq[1]; base = i - 4096; }
            else                { W = W2; dst = g_Wq[2]; base = i - 8192; }
            const int c = base & 127, k4 = base >> 7;
            const float v0 = W[(4 * k4 + 0) * 128 + c];
            const float v1 = W[(4 * k4 + 1) * 128 + c];
            const float v2 = W[(4 * k4 + 2) * 128 + c];
            const float v3 = W[(4 * k4 + 3) * 128 + c];
            ulonglong2 q; q.x = packf2(v0, v1); q.y = packf2(v2, v3);
            dst[base] = q;
        } else if (i < 16384) { // fp16 8-pack of Wc1
            const int base = i - 10240;
            const int c = base & 127, k8 = base >> 7;
            unsigned hb[4];
#pragma unroll
            for (int t = 0; t < 4; t++) {
                const __half2 h = __floats2half2_rn(
                    Wc1[(8 * k8 + 2 * t) * 128 + c],
                    Wc1[(8 * k8 + 2 * t + 1) * 128 + c]);
                hb[t] = *reinterpret_cast<const unsigned*>(&h);
            }
            ulonglong2 q;
            q.x = (u64)hb[0] | ((u64)hb[1] << 32);
            q.y = (u64)hb[2] | ((u64)hb[3] << 32);
            g_Wc1h[base] = q;
        }
    } else {                    // histogram role
        const int g = (blockIdx.x - 64) * 256 + threadIdx.x;
        if (g >= 3 * EE) return;
        const int cat = g / EE, le = g - cat * EE;
        const int* ei = cat == 0 ? e0 : (cat == 1 ? e1 : e2);
        atomicAdd(&g_deg[cat][ei[EE + le]], 1);
    }
}

// ---------------- k1: CSR scan -------------------------------------------------
__global__ void scan3_kernel()
{
    const int cat = blockIdx.x;
    const int* deg = g_deg[cat];
    int* rowptr = g_rowptr[cat];
    int* cur = g_cur[cat];
    const int t = threadIdx.x;              // 0..1023
    const int CH = (NN + 1023) / 1024;      // 40
    const int lo = t * CH;
    const int hi = min(lo + CH, NN);
    int s = 0;
    for (int i = lo; i < hi; i++) s += deg[i];
    __shared__ int wsum[32];
    const int lane = t & 31, wid = t >> 5;
    int v = s;
#pragma unroll
    for (int o = 1; o < 32; o <<= 1) {
        const int u = __shfl_up_sync(0xFFFFFFFFu, v, o);
        if (lane >= o) v += u;
    }
    if (lane == 31) wsum[wid] = v;
    __syncthreads();
    if (wid == 0) {
        int u = wsum[lane];
#pragma unroll
        for (int o = 1; o < 32; o <<= 1) {
            const int t2 = __shfl_up_sync(0xFFFFFFFFu, u, o);
            if (lane >= o) u += t2;
        }
        wsum[lane] = u;
    }
    __syncthreads();
    int run = v - s + (wid ? wsum[wid - 1] : 0);
    for (int i = lo; i < hi; i++) {
        rowptr[i] = run; cur[i] = run; run += deg[i];
    }
    if (t == 1023) rowptr[NN] = run;
}

// ---------------- GEMM body: xw = x @ W + fused attention dots ---------------
template <int DIN>
__device__ __forceinline__ void gemm_body(const float* __restrict__ x,
                                          const ulonglong2* __restrict__ Wq,
                                          const float* __restrict__ att_s,
                                          const float* __restrict__ att_d,
                                          __half* __restrict__ xw,
                                          float* __restrict__ as_,
                                          float* __restrict__ ad_,
                                          int r2, int stride, float* xs,
                                          float (*redbuf)[8][2])
{
    const int c = threadIdx.x;              // 0..127 output column
    const float vs = att_s[c];
    const float vd = att_d[c];
    const int w = c >> 5;
    for (int g = r2; g < NN / 8; g += stride) {
        const int n0 = g * 8;
        __syncthreads();
        for (int i = c; i < 8 * DIN / 4; i += 128)
            reinterpret_cast<float4*>(xs)[i] =
                reinterpret_cast<const float4*>(x + n0 * DIN)[i];
        __syncthreads();
        u64 acc2[8];
#pragma unroll
        for (int r = 0; r < 8; r++) acc2[r] = 0ull;
#pragma unroll 4
        for (int k4 = 0; k4 < DIN / 4; k4++) {
            const ulonglong2 wp = Wq[k4 * 128 + c];
#pragma unroll
            for (int r = 0; r < 8; r++) {
                const ulonglong2 a =
                    *reinterpret_cast<const ulonglong2*>(&xs[r * DIN + 4 * k4]);
                ffma2(acc2[r], a.x, wp.x);
                ffma2(acc2[r], a.y, wp.y);
            }
        }
#pragma unroll
        for (int r = 0; r < 8; r++) {
            const float accr = unpack_sum(acc2[r]);
            xw[(n0 + r) * HC + c] = __float2half_rn(accr);
            float ps = accr * vs, pd = accr * vd;
#pragma unroll
            for (int o = 16; o; o >>= 1) {
                ps += __shfl_down_sync(0xFFFFFFFFu, ps, o);
                pd += __shfl_down_sync(0xFFFFFFFFu, pd, o);
            }
            if ((c & 31) == 0) { redbuf[w][r][0] = ps; redbuf[w][r][1] = pd; }
        }
        __syncthreads();
        if (c < 16) {               // c encodes (r, h)
            const int r = c >> 1, h = c & 1;
            as_[(n0 + r) * 2 + h] = redbuf[2 * h][r][0] + redbuf[2 * h + 1][r][0];
            ad_[(n0 + r) * 2 + h] = redbuf[2 * h][r][1] + redbuf[2 * h + 1][r][1];
        }
    }
}

// ---------------- k2: 3 GEMMs + CSR scatter in one heterogeneous grid ---------
__global__ void __launch_bounds__(128)
phase1_kernel(const float* __restrict__ x0, const float* __restrict__ x1,
              const float* __restrict__ x2,
              const float* __restrict__ s0, const float* __restrict__ s1,
              const float* __restrict__ s2,
              const float* __restrict__ t0, const float* __restrict__ t1,
              const float* __restrict__ t2,
              const int* __restrict__ e0, const int* __restrict__ e1,
              const int* __restrict__ e2)
{
    __shared__ __align__(16) float xs[8 * 128];
    __shared__ float redbuf[4][8][2];
    const int role = blockIdx.x % ROLES;
    const int rank = blockIdx.x / ROLES;
    if (role < 4)
        gemm_body<128>(x0, g_Wq[0], s0, t0, g_xw[0], g_as[0], g_ad[0],
                       role * RPB + rank, 4 * RPB, xs, redbuf);
    else if (role < 8)
        gemm_body<128>(x1, g_Wq[1], s1, t1, g_xw[1], g_as[1], g_ad[1],
                       (role - 4) * RPB + rank, 4 * RPB, xs, redbuf);
    else if (role < 10)
        gemm_body<64>(x2, g_Wq[2], s2, t2, g_xw[2], g_as[2], g_ad[2],
                      (role - 8) * RPB + rank, 2 * RPB, xs, redbuf);
    else {                      // scatter role: build g_srt (independent of GEMM)
        const int stride = RPB * 128;
        for (int g = rank * 128 + threadIdx.x; g < 3 * EE; g += stride) {
            const int cat = g / EE, le = g - cat * EE;
            const int* ei = cat == 0 ? e0 : (cat == 1 ? e1 : e2);
            const int pos = atomicAdd(&g_cur[cat][ei[EE + le]], 1);
            g_srt[cat][pos] = ei[le];
        }
    }
}

// ---------------- k3: fused gather + softmax + ELU + MLP (16 nodes/block) -----
__global__ void __launch_bounds__(256)
gather_mlp_kernel(const float* __restrict__ b0, const float* __restrict__ b1,
                  const float* __restrict__ b2,
                  const float* __restrict__ bc1, const float* __restrict__ Wc2,
                  const float* __restrict__ bc2, float* __restrict__ out)
{
    __shared__ __align__(16) float hs[16 * FUSED];
    __shared__ __align__(16) int4 recs[8][32];     // per-warp edge-record stage
    __shared__ float redm[8][8];
    const int tid = threadIdx.x, wid = tid >> 5, lane = tid & 31;
    const int n0 = blockIdx.x * 16;
    const int h = lane >> 4;                  // lanes 0-15 head0, 16-31 head1

    // -------- gather: each warp processes rows wid and wid+8 ------------------
    for (int cat = 0; cat < 3; cat++) {
        const float*  as_ = g_as[cat];
        const __half* xw  = g_xw[cat];
        const int*    srt = g_srt[cat];
        const float*  bias = cat == 0 ? b0 : (cat == 1 ? b1 : b2);

#pragma unroll
        for (int rep = 0; rep < 2; rep++) {
            const int row = wid + rep * 8;
            const int dst = n0 + row;

            const float2 ad2 = *reinterpret_cast<const float2*>(&g_ad[cat][dst * 2]);
            const float2 as2 = __ldg(reinterpret_cast<const float2*>(as_) + dst);
            float t0 = as2.x + ad2.x; t0 = t0 > 0.f ? t0 : 0.2f * t0;
            float t1 = as2.y + ad2.y; t1 = t1 > 0.f ? t1 : 0.2f * t1;
            const float exs0 = __expf(t0), exs1 = __expf(t1);
            float d0 = (lane == 0) ? exs0 : 0.f;
            float d1 = (lane == 0) ? exs1 : 0.f;
            const float exself = h ? exs1 : exs0;
            const uint2 sv = __ldg(reinterpret_cast<const uint2*>(
                                       xw + (size_t)dst * HC) + lane);
            float2 sa = __half22float2(*reinterpret_cast<const __half2*>(&sv.x));
            float2 sb = __half22float2(*reinterpret_cast<const __half2*>(&sv.y));
            float4 acc = make_float4(sa.x * exself, sa.y * exself,
                                     sb.x * exself, sb.y * exself);

            const int start = __ldg(&g_rowptr[cat][dst]);
            const int end   = __ldg(&g_rowptr[cat][dst + 1]);
            for (int p = start; p < end; p += 32) {
                const int n = min(32, end - p);
                const int mysrc = (lane < n) ? __ldg(srt + p + lane) : 0;
                const float2 a = __ldg(reinterpret_cast<const float2*>(as_) + mysrc);
                float u0 = a.x + ad2.x; u0 = u0 > 0.f ? u0 : 0.2f * u0;
                float u1 = a.y + ad2.y; u1 = u1 > 0.f ? u1 : 0.2f * u1;
                const float x0 = __expf(u0), x1 = __expf(u1);
                if (lane < n) { d0 += x0; d1 += x1; }
                recs[wid][lane] = make_int4(mysrc, __float_as_int(x0),
                                            __float_as_int(x1), 0);
                __syncwarp();
#pragma unroll 4
                for (int i = 0; i < n; i++) {
                    const int4 rec = recs[wid][i];     // broadcast LDS
                    const float exh = h ? __int_as_float(rec.z)
                                        : __int_as_float(rec.y);
                    const uint2 uv = __ldg(reinterpret_cast<const uint2*>(
                                               xw + (size_t)rec.x * HC) + lane);
                    float2 fa = __half22float2(
                        *reinterpret_cast<const __half2*>(&uv.x));
                    float2 fb = __half22float2(
                        *reinterpret_cast<const __half2*>(&uv.y));
                    acc.x += fa.x * exh; acc.y += fa.y * exh;
                    acc.z += fb.x * exh; acc.w += fb.y * exh;
                }
                __syncwarp();
            }
#pragma unroll
            for (int o = 16; o; o >>= 1) {
                d0 += __shfl_xor_sync(0xFFFFFFFFu, d0, o);
                d1 += __shfl_xor_sync(0xFFFFFFFFu, d1, o);
            }
            const float inv = __fdividef(1.f, h ? d1 : d0);
            const int col = lane * 4;
            float4 o;
            o.x = acc.x * inv + bias[col + 0]; o.x = o.x > 0.f ? o.x : expm1f(o.x);
            o.y = acc.y * inv + bias[col + 1]; o.y = o.y > 0.f ? o.y : expm1f(o.y);
            o.z = acc.z * inv + bias[col + 2]; o.z = o.z > 0.f ? o.z : expm1f(o.z);
            o.w = acc.w * inv + bias[col + 3]; o.w = o.w > 0.f ? o.w : expm1f(o.w);
            *reinterpret_cast<float4*>(&hs[row * FUSED + cat * HC + col]) = o;
        }
    }
    __syncthreads();

    // ---- MLP: two 128-thread groups, full-K over own 8 rows, fp16 Wc1 --------
    const int j = tid & 127;           // hidden unit
    const int grp = tid >> 7;          // 0 -> rows 0-7, 1 -> rows 8-15
    u64 acc2[8];
#pragma unroll
    for (int r = 0; r < 8; r++) acc2[r] = 0ull;
#pragma unroll 2
    for (int k8 = 0; k8 < FUSED / 8; k8++) {
        const ulonglong2 wp = g_Wc1h[k8 * 128 + j];   // 8 fp16 k-values
        const u64 w01 = h2_to_u64f2((unsigned)(wp.x));
        const u64 w23 = h2_to_u64f2((unsigned)(wp.x >> 32));
        const u64 w45 = h2_to_u64f2((unsigned)(wp.y));
        const u64 w67 = h2_to_u64f2((unsigned)(wp.y >> 32));
#pragma unroll
        for (int r = 0; r < 8; r++) {
            const float* hrow = &hs[(grp * 8 + r) * FUSED + 8 * k8];
            const ulonglong2 a0 = *reinterpret_cast<const ulonglong2*>(hrow);
            const ulonglong2 a1 = *reinterpret_cast<const ulonglong2*>(hrow + 4);
            ffma2(acc2[r], a0.x, w01);
            ffma2(acc2[r], a0.y, w23);
            ffma2(acc2[r], a1.x, w45);
            ffma2(acc2[r], a1.y, w67);
        }
    }
    const float w2c = Wc2[j];
    const float b1c = bc1[j];
#pragma unroll
    for (int r = 0; r < 8; r++) {
        float hv = unpack_sum(acc2[r]) + b1c;
        hv = fmaxf(hv, 0.f);
        float p = hv * w2c;
#pragma unroll
        for (int o = 16; o; o >>= 1) p += __shfl_down_sync(0xFFFFFFFFu, p, o);
        if (lane == 0) redm[wid][r] = p;   // wid 0-3: rows 0-7; wid 4-7: rows 8-15
    }
    __syncthreads();
    if (tid < 16) {
        const int grp2 = tid >> 3;         // which group owns this row
        const int r = tid & 7;
        const int wbase = grp2 * 4;
        out[n0 + tid] = redm[wbase + 0][r] + redm[wbase + 1][r] +
                        redm[wbase + 2][r] + redm[wbase + 3][r] + bc2[0];
    }
}

// ---------------- host orchestration ------------------------------------------
extern "C" void kernel_launch(void* const* d_in, const int* in_sizes, int n_in,
                              void* d_out, int out_size)
{
    const float* x[3];  const int* ei[3];  const float* W[3];
    const float* atts[3]; const float* attd[3]; const float* bias[3];
    for (int i = 0; i < 3; i++) {
        x[i]    = (const float*)d_in[6 * i + 0];
        ei[i]   = (const int*)  d_in[6 * i + 1];
        W[i]    = (const float*)d_in[6 * i + 2];
        atts[i] = (const float*)d_in[6 * i + 3];
        attd[i] = (const float*)d_in[6 * i + 4];
        bias[i] = (const float*)d_in[6 * i + 5];
    }
    const float* Wc1 = (const float*)d_in[18];
    const float* bc1 = (const float*)d_in[19];
    const float* Wc2 = (const float*)d_in[20];
    const float* bc2 = (const float*)d_in[21];
    float* out = (float*)d_out;

    int* p_deg;
    cudaGetSymbolAddress((void**)&p_deg, g_deg);
    cudaMemsetAsync(p_deg, 0, sizeof(int) * 3 * NN);

    // k0: pack+hist   k1: scan   k2: phase1   k3: gather_mlp (capture slot)
    pack_hist_kernel<<<64 + (3 * EE + 255) / 256, 256>>>(
        W[0], W[1], W[2], Wc1, ei[0], ei[1], ei[2]);

    scan3_kernel<<<3, 1024>>>();

    phase1_kernel<<<P1GRID, 128>>>(x[0], x[1], x[2],
                                   atts[0], atts[1], atts[2],
                                   attd[0], attd[1], attd[2],
                                   ei[0], ei[1], ei[2]);

    gather_mlp_kernel<<<NN / 16, 256>>>(bias[0], bias[1], bias[2],
                                        bc1, Wc2, bc2, out);
}

// round 15
// speedup vs baseline: 1.1365x; 1.0046x over previous
#include <cuda_runtime.h>
#include <cuda_fp16.h>
#include <math.h>

#define NN 40000
#define EE 600000
#define HC 128          // H*C
#define FUSED 384
#define ROLES 11        // 4 cat0 + 4 cat1 + 2 cat2 + 1 scatter
#define RPB 431         // ranks per role
#define P1GRID (ROLES * RPB)

typedef unsigned long long u64;

// ---------------- scratch (device globals; no allocation allowed) -------------
__device__ __align__(16) __half g_xw[3][NN * HC];  // transformed features (fp16)
__device__ __align__(8)  float g_as[3][NN * 2];    // a_src per node/head
__device__ __align__(8)  float g_ad[3][NN * 2];    // a_dst per node/head
__device__ int        g_deg[3][NN];
__device__ int        g_rowptr[3][NN + 1];
__device__ int        g_cur[3][NN];
__device__ int        g_srt[3][EE];                // src ids sorted by dst
__device__ ulonglong2 g_Wq[3][4096];               // quad-packed W (fp32 k-quads)
__device__ ulonglong2 g_Wc1h[6144];                // fp16-packed Wc1 (8 k / 16B)

__device__ __forceinline__ void ffma2(u64& acc, u64 a, u64 b)
{
    asm("fma.rn.f32x2 %0, %1, %2, %0;" : "+l"(acc) : "l"(a), "l"(b));
}
__device__ __forceinline__ float unpack_sum(u64 v)
{
    float lo, hi;
    asm("mov.b64 {%0,%1}, %2;" : "=f"(lo), "=f"(hi) : "l"(v));
    return lo + hi;
}
__device__ __forceinline__ u64 packf2(float lo, float hi)
{
    u64 r; asm("mov.b64 %0, {%1,%2};" : "=l"(r) : "f"(lo), "f"(hi)); return r;
}
__device__ __forceinline__ u64 h2_to_u64f2(unsigned h2bits)
{
    const float2 f = __half22float2(*reinterpret_cast<const __half2*>(&h2bits));
    return packf2(f.x, f.y);
}

// ---------------- k0: weight pre-pack + degree histogram ----------------------
__global__ void __launch_bounds__(256)
pack_hist_kernel(const float* __restrict__ W0, const float* __restrict__ W1,
                 const float* __restrict__ W2, const float* __restrict__ Wc1,
                 const int* __restrict__ e0, const int* __restrict__ e1,
                 const int* __restrict__ e2)
{
    if (blockIdx.x < 64) {      // pack role
        const int i = blockIdx.x * 256 + threadIdx.x;
        if (i < 10240) {        // fp32 quad-pack of the three GAT weights
            const float* W; ulonglong2* dst; int base;
            if      (i <  4096) { W = W0; dst = g_Wq[0]; base = i; }
            else if (i <  8192) { W = W1; dst = g_Wq[1]; base = i - 4096; }
            else                { W = W2; dst = g_Wq[2]; base = i - 8192; }
            const int c = base & 127, k4 = base >> 7;
            const float v0 = W[(4 * k4 + 0) * 128 + c];
            const float v1 = W[(4 * k4 + 1) * 128 + c];
            const float v2 = W[(4 * k4 + 2) * 128 + c];
            const float v3 = W[(4 * k4 + 3) * 128 + c];
            ulonglong2 q; q.x = packf2(v0, v1); q.y = packf2(v2, v3);
            dst[base] = q;
        } else if (i < 16384) { // fp16 8-pack of Wc1
            const int base = i - 10240;
            const int c = base & 127, k8 = base >> 7;
            unsigned hb[4];
#pragma unroll
            for (int t = 0; t < 4; t++) {
                const __half2 h = __floats2half2_rn(
                    Wc1[(8 * k8 + 2 * t) * 128 + c],
                    Wc1[(8 * k8 + 2 * t + 1) * 128 + c]);
                hb[t] = *reinterpret_cast<const unsigned*>(&h);
            }
            ulonglong2 q;
            q.x = (u64)hb[0] | ((u64)hb[1] << 32);
            q.y = (u64)hb[2] | ((u64)hb[3] << 32);
            g_Wc1h[base] = q;
        }
    } else {                    // histogram role
        const int g = (blockIdx.x - 64) * 256 + threadIdx.x;
        if (g >= 3 * EE) return;
        const int cat = g / EE, le = g - cat * EE;
        const int* ei = cat == 0 ? e0 : (cat == 1 ? e1 : e2);
        atomicAdd(&g_deg[cat][ei[EE + le]], 1);
    }
}

// ---------------- k1: CSR scan -------------------------------------------------
__global__ void scan3_kernel()
{
    const int cat = blockIdx.x;
    const int* deg = g_deg[cat];
    int* rowptr = g_rowptr[cat];
    int* cur = g_cur[cat];
    const int t = threadIdx.x;              // 0..1023
    const int CH = (NN + 1023) / 1024;      // 40
    const int lo = t * CH;
    const int hi = min(lo + CH, NN);
    int s = 0;
    for (int i = lo; i < hi; i++) s += deg[i];
    __shared__ int wsum[32];
    const int lane = t & 31, wid = t >> 5;
    int v = s;
#pragma unroll
    for (int o = 1; o < 32; o <<= 1) {
        const int u = __shfl_up_sync(0xFFFFFFFFu, v, o);
        if (lane >= o) v += u;
    }
    if (lane == 31) wsum[wid] = v;
    __syncthreads();
    if (wid == 0) {
        int u = wsum[lane];
#pragma unroll
        for (int o = 1; o < 32; o <<= 1) {
            const int t2 = __shfl_up_sync(0xFFFFFFFFu, u, o);
            if (lane >= o) u += t2;
        }
        wsum[lane] = u;
    }
    __syncthreads();
    int run = v - s + (wid ? wsum[wid - 1] : 0);
    for (int i = lo; i < hi; i++) {
        rowptr[i] = run; cur[i] = run; run += deg[i];
    }
    if (t == 1023) rowptr[NN] = run;
}

// ---------------- GEMM body: xw = x @ W + fused attention dots ---------------
template <int DIN>
__device__ __forceinline__ void gemm_body(const float* __restrict__ x,
                                          const ulonglong2* __restrict__ Wq,
                                          const float* __restrict__ att_s,
                                          const float* __restrict__ att_d,
                                          __half* __restrict__ xw,
                                          float* __restrict__ as_,
                                          float* __restrict__ ad_,
                                          int r2, int stride, float* xs,
                                          float (*redbuf)[8][2])
{
    const int c = threadIdx.x;              // 0..127 output column
    const float vs = att_s[c];
    const float vd = att_d[c];
    const int w = c >> 5;
    for (int g = r2; g < NN / 8; g += stride) {
        const int n0 = g * 8;
        __syncthreads();
        for (int i = c; i < 8 * DIN / 4; i += 128)
            reinterpret_cast<float4*>(xs)[i] =
                reinterpret_cast<const float4*>(x + n0 * DIN)[i];
        __syncthreads();
        u64 acc2[8];
#pragma unroll
        for (int r = 0; r < 8; r++) acc2[r] = 0ull;
#pragma unroll 4
        for (int k4 = 0; k4 < DIN / 4; k4++) {
            const ulonglong2 wp = Wq[k4 * 128 + c];
#pragma unroll
            for (int r = 0; r < 8; r++) {
                const ulonglong2 a =
                    *reinterpret_cast<const ulonglong2*>(&xs[r * DIN + 4 * k4]);
                ffma2(acc2[r], a.x, wp.x);
                ffma2(acc2[r], a.y, wp.y);
            }
        }
#pragma unroll
        for (int r = 0; r < 8; r++) {
            const float accr = unpack_sum(acc2[r]);
            xw[(n0 + r) * HC + c] = __float2half_rn(accr);
            float ps = accr * vs, pd = accr * vd;
#pragma unroll
            for (int o = 16; o; o >>= 1) {
                ps += __shfl_down_sync(0xFFFFFFFFu, ps, o);
                pd += __shfl_down_sync(0xFFFFFFFFu, pd, o);
            }
            if ((c & 31) == 0) { redbuf[w][r][0] = ps; redbuf[w][r][1] = pd; }
        }
        __syncthreads();
        if (c < 16) {               // c encodes (r, h)
            const int r = c >> 1, h = c & 1;
            as_[(n0 + r) * 2 + h] = redbuf[2 * h][r][0] + redbuf[2 * h + 1][r][0];
            ad_[(n0 + r) * 2 + h] = redbuf[2 * h][r][1] + redbuf[2 * h + 1][r][1];
        }
    }
}

// ---------------- k2: 3 GEMMs + CSR scatter in one heterogeneous grid ---------
__global__ void __launch_bounds__(128)
phase1_kernel(const float* __restrict__ x0, const float* __restrict__ x1,
              const float* __restrict__ x2,
              const float* __restrict__ s0, const float* __restrict__ s1,
              const float* __restrict__ s2,
              const float* __restrict__ t0, const float* __restrict__ t1,
              const float* __restrict__ t2,
              const int* __restrict__ e0, const int* __restrict__ e1,
              const int* __restrict__ e2)
{
    __shared__ __align__(16) float xs[8 * 128];
    __shared__ float redbuf[4][8][2];
    const int role = blockIdx.x % ROLES;
    const int rank = blockIdx.x / ROLES;
    if (role < 4)
        gemm_body<128>(x0, g_Wq[0], s0, t0, g_xw[0], g_as[0], g_ad[0],
                       role * RPB + rank, 4 * RPB, xs, redbuf);
    else if (role < 8)
        gemm_body<128>(x1, g_Wq[1], s1, t1, g_xw[1], g_as[1], g_ad[1],
                       (role - 4) * RPB + rank, 4 * RPB, xs, redbuf);
    else if (role < 10)
        gemm_body<64>(x2, g_Wq[2], s2, t2, g_xw[2], g_as[2], g_ad[2],
                      (role - 8) * RPB + rank, 2 * RPB, xs, redbuf);
    else {                      // scatter role: build g_srt (independent of GEMM)
        const int stride = RPB * 128;
        for (int g = rank * 128 + threadIdx.x; g < 3 * EE; g += stride) {
            const int cat = g / EE, le = g - cat * EE;
            const int* ei = cat == 0 ? e0 : (cat == 1 ? e1 : e2);
            const int pos = atomicAdd(&g_cur[cat][ei[EE + le]], 1);
            g_srt[cat][pos] = ei[le];
        }
    }
}

// ---------------- k3: fused gather + softmax + ELU + MLP (16 nodes/block) -----
__global__ void __launch_bounds__(256, 5)
gather_mlp_kernel(const float* __restrict__ b0, const float* __restrict__ b1,
                  const float* __restrict__ b2,
                  const float* __restrict__ bc1, const float* __restrict__ Wc2,
                  const float* __restrict__ bc2, float* __restrict__ out)
{
    __shared__ __align__(16) float hs[16 * FUSED];
    __shared__ __align__(16) int4 recs[8][32];     // per-warp edge-record stage
    __shared__ float redm[8][8];
    const int tid = threadIdx.x, wid = tid >> 5, lane = tid & 31;
    const int n0 = blockIdx.x * 16;
    const int h = lane >> 4;                  // lanes 0-15 head0, 16-31 head1

    // -------- gather: each warp processes rows wid and wid+8 ------------------
    for (int cat = 0; cat < 3; cat++) {
        const float*  as_ = g_as[cat];
        const __half* xw  = g_xw[cat];
        const int*    srt = g_srt[cat];
        const float*  bias = cat == 0 ? b0 : (cat == 1 ? b1 : b2);

#pragma unroll
        for (int rep = 0; rep < 2; rep++) {
            const int row = wid + rep * 8;
            const int dst = n0 + row;

            const float2 ad2 = *reinterpret_cast<const float2*>(&g_ad[cat][dst * 2]);
            const float2 as2 = __ldg(reinterpret_cast<const float2*>(as_) + dst);
            float t0 = as2.x + ad2.x; t0 = t0 > 0.f ? t0 : 0.2f * t0;
            float t1 = as2.y + ad2.y; t1 = t1 > 0.f ? t1 : 0.2f * t1;
            const float exs0 = __expf(t0), exs1 = __expf(t1);
            float d0 = (lane == 0) ? exs0 : 0.f;
            float d1 = (lane == 0) ? exs1 : 0.f;
            const float exself = h ? exs1 : exs0;
            const uint2 sv = __ldg(reinterpret_cast<const uint2*>(
                                       xw + (size_t)dst * HC) + lane);
            float2 sa = __half22float2(*reinterpret_cast<const __half2*>(&sv.x));
            float2 sb = __half22float2(*reinterpret_cast<const __half2*>(&sv.y));
            float4 acc = make_float4(sa.x * exself, sa.y * exself,
                                     sb.x * exself, sb.y * exself);

            const int start = __ldg(&g_rowptr[cat][dst]);
            const int end   = __ldg(&g_rowptr[cat][dst + 1]);
            for (int p = start; p < end; p += 32) {
                const int n = min(32, end - p);
                const int mysrc = (lane < n) ? __ldg(srt + p + lane) : 0;
                const float2 a = __ldg(reinterpret_cast<const float2*>(as_) + mysrc);
                float u0 = a.x + ad2.x; u0 = u0 > 0.f ? u0 : 0.2f * u0;
                float u1 = a.y + ad2.y; u1 = u1 > 0.f ? u1 : 0.2f * u1;
                const float x0 = __expf(u0), x1 = __expf(u1);
                if (lane < n) { d0 += x0; d1 += x1; }
                recs[wid][lane] = make_int4(mysrc, __float_as_int(x0),
                                            __float_as_int(x1), 0);
                __syncwarp();
#pragma unroll 4
                for (int i = 0; i < n; i++) {
                    const int4 rec = recs[wid][i];     // broadcast LDS
                    const float exh = h ? __int_as_float(rec.z)
                                        : __int_as_float(rec.y);
                    const uint2 uv = __ldg(reinterpret_cast<const uint2*>(
                                               xw + (size_t)rec.x * HC) + lane);
                    float2 fa = __half22float2(
                        *reinterpret_cast<const __half2*>(&uv.x));
                    float2 fb = __half22float2(
                        *reinterpret_cast<const __half2*>(&uv.y));
                    acc.x += fa.x * exh; acc.y += fa.y * exh;
                    acc.z += fb.x * exh; acc.w += fb.y * exh;
                }
                __syncwarp();
            }
#pragma unroll
            for (int o = 16; o; o >>= 1) {
                d0 += __shfl_xor_sync(0xFFFFFFFFu, d0, o);
                d1 += __shfl_xor_sync(0xFFFFFFFFu, d1, o);
            }
            const float inv = __fdividef(1.f, h ? d1 : d0);
            const int col = lane * 4;
            float4 o;
            o.x = acc.x * inv + bias[col + 0]; o.x = o.x > 0.f ? o.x : expm1f(o.x);
            o.y = acc.y * inv + bias[col + 1]; o.y = o.y > 0.f ? o.y : expm1f(o.y);
            o.z = acc.z * inv + bias[col + 2]; o.z = o.z > 0.f ? o.z : expm1f(o.z);
            o.w = acc.w * inv + bias[col + 3]; o.w = o.w > 0.f ? o.w : expm1f(o.w);
            *reinterpret_cast<float4*>(&hs[row * FUSED + cat * HC + col]) = o;
        }
    }
    __syncthreads();

    // ---- MLP: two 128-thread groups, full-K over own 8 rows, fp16 Wc1 --------
    const int j = tid & 127;           // hidden unit
    const int grp = tid >> 7;          // 0 -> rows 0-7, 1 -> rows 8-15
    u64 acc2[8];
#pragma unroll
    for (int r = 0; r < 8; r++) acc2[r] = 0ull;
#pragma unroll 2
    for (int k8 = 0; k8 < FUSED / 8; k8++) {
        const ulonglong2 wp = g_Wc1h[k8 * 128 + j];   // 8 fp16 k-values
        const u64 w01 = h2_to_u64f2((unsigned)(wp.x));
        const u64 w23 = h2_to_u64f2((unsigned)(wp.x >> 32));
        const u64 w45 = h2_to_u64f2((unsigned)(wp.y));
        const u64 w67 = h2_to_u64f2((unsigned)(wp.y >> 32));
#pragma unroll
        for (int r = 0; r < 8; r++) {
            const float* hrow = &hs[(grp * 8 + r) * FUSED + 8 * k8];
            const ulonglong2 a0 = *reinterpret_cast<const ulonglong2*>(hrow);
            const ulonglong2 a1 = *reinterpret_cast<const ulonglong2*>(hrow + 4);
            ffma2(acc2[r], a0.x, w01);
            ffma2(acc2[r], a0.y, w23);
            ffma2(acc2[r], a1.x, w45);
            ffma2(acc2[r], a1.y, w67);
        }
    }
    const float w2c = Wc2[j];
    const float b1c = bc1[j];
#pragma unroll
    for (int r = 0; r < 8; r++) {
        float hv = unpack_sum(acc2[r]) + b1c;
        hv = fmaxf(hv, 0.f);
        float p = hv * w2c;
#pragma unroll
        for (int o = 16; o; o >>= 1) p += __shfl_down_sync(0xFFFFFFFFu, p, o);
        if (lane == 0) redm[wid][r] = p;   // wid 0-3: rows 0-7; wid 4-7: rows 8-15
    }
    __syncthreads();
    if (tid < 16) {
        const int grp2 = tid >> 3;         // which group owns this row
        const int r = tid & 7;
        const int wbase = grp2 * 4;
        out[n0 + tid] = redm[wbase + 0][r] + redm[wbase + 1][r] +
                        redm[wbase + 2][r] + redm[wbase + 3][r] + bc2[0];
    }
}

// ---------------- host orchestration ------------------------------------------
extern "C" void kernel_launch(void* const* d_in, const int* in_sizes, int n_in,
                              void* d_out, int out_size)
{
    const float* x[3];  const int* ei[3];  const float* W[3];
    const float* atts[3]; const float* attd[3]; const float* bias[3];
    for (int i = 0; i < 3; i++) {
        x[i]    = (const float*)d_in[6 * i + 0];
        ei[i]   = (const int*)  d_in[6 * i + 1];
        W[i]    = (const float*)d_in[6 * i + 2];
        atts[i] = (const float*)d_in[6 * i + 3];
        attd[i] = (const float*)d_in[6 * i + 4];
        bias[i] = (const float*)d_in[6 * i + 5];
    }
    const float* Wc1 = (const float*)d_in[18];
    const float* bc1 = (const float*)d_in[19];
    const float* Wc2 = (const float*)d_in[20];
    const float* bc2 = (const float*)d_in[21];
    float* out = (float*)d_out;

    int* p_deg;
    cudaGetSymbolAddress((void**)&p_deg, g_deg);
    cudaMemsetAsync(p_deg, 0, sizeof(int) * 3 * NN);

    // k0: pack+hist   k1: scan   k2: phase1   k3: gather_mlp (capture slot)
    pack_hist_kernel<<<64 + (3 * EE + 255) / 256, 256>>>(
        W[0], W[1], W[2], Wc1, ei[0], ei[1], ei[2]);

    scan3_kernel<<<3, 1024>>>();

    phase1_kernel<<<P1GRID, 128>>>(x[0], x[1], x[2],
                                   atts[0], atts[1], atts[2],
                                   attd[0], attd[1], attd[2],
                                   ei[0], ei[1], ei[2]);

    gather_mlp_kernel<<<NN / 16, 256>>>(bias[0], bias[1], bias[2],
                                        bc1, Wc2, bc2, out);
}

// round 16
// speedup vs baseline: 1.1517x; 1.0134x over previous
#include <cuda_runtime.h>
#include <cuda_fp16.h>
#include <math.h>

#define NN 40000
#define EE 600000
#define HC 128          // H*C
#define FUSED 384
#define ROLES 11        // 4 cat0 + 4 cat1 + 2 cat2 + 1 scatter
#define RPB 431         // ranks per role
#define P1GRID (ROLES * RPB)
#define NHB 879         // hist blocks: ceil(3*EE/8/256)

typedef unsigned long long u64;

// ---------------- scratch (device globals; no allocation allowed) -------------
__device__ __align__(16) __half g_xw[3][NN * HC];  // transformed features (fp16)
__device__ __align__(8)  float g_as[3][NN * 2];    // a_src per node/head
__device__ __align__(8)  float g_ad[3][NN * 2];    // a_dst per node/head
__device__ int        g_deg[3][NN];
__device__ int        g_rowptr[3][NN + 1];
__device__ int        g_cur[3][NN];
__device__ int        g_srt[3][EE];                // src ids sorted by dst
__device__ ulonglong2 g_Wq[3][4096];               // quad-packed W (fp32 k-quads)
__device__ ulonglong2 g_Wc1h[6144];                // fp16-packed Wc1 (8 k / 16B)

__device__ __forceinline__ void ffma2(u64& acc, u64 a, u64 b)
{
    asm("fma.rn.f32x2 %0, %1, %2, %0;" : "+l"(acc) : "l"(a), "l"(b));
}
__device__ __forceinline__ float unpack_sum(u64 v)
{
    float lo, hi;
    asm("mov.b64 {%0,%1}, %2;" : "=f"(lo), "=f"(hi) : "l"(v));
    return lo + hi;
}
__device__ __forceinline__ u64 packf2(float lo, float hi)
{
    u64 r; asm("mov.b64 %0, {%1,%2};" : "=l"(r) : "f"(lo), "f"(hi)); return r;
}
__device__ __forceinline__ u64 h2_to_u64f2(unsigned h2bits)
{
    const float2 f = __half22float2(*reinterpret_cast<const __half2*>(&h2bits));
    return packf2(f.x, f.y);
}

// ---------------- k0: weight pre-pack + batched degree histogram --------------
__global__ void __launch_bounds__(256)
pack_hist_kernel(const float* __restrict__ W0, const float* __restrict__ W1,
                 const float* __restrict__ W2, const float* __restrict__ Wc1,
                 const int* __restrict__ e0, const int* __restrict__ e1,
                 const int* __restrict__ e2)
{
    if (blockIdx.x < 64) {      // pack role
        const int i = blockIdx.x * 256 + threadIdx.x;
        if (i < 10240) {        // fp32 quad-pack of the three GAT weights
            const float* W; ulonglong2* dst; int base;
            if      (i <  4096) { W = W0; dst = g_Wq[0]; base = i; }
            else if (i <  8192) { W = W1; dst = g_Wq[1]; base = i - 4096; }
            else                { W = W2; dst = g_Wq[2]; base = i - 8192; }
            const int c = base & 127, k4 = base >> 7;
            const float v0 = W[(4 * k4 + 0) * 128 + c];
            const float v1 = W[(4 * k4 + 1) * 128 + c];
            const float v2 = W[(4 * k4 + 2) * 128 + c];
            const float v3 = W[(4 * k4 + 3) * 128 + c];
            ulonglong2 q; q.x = packf2(v0, v1); q.y = packf2(v2, v3);
            dst[base] = q;
        } else if (i < 16384) { // fp16 8-pack of Wc1
            const int base = i - 10240;
            const int c = base & 127, k8 = base >> 7;
            unsigned hb[4];
#pragma unroll
            for (int t = 0; t < 4; t++) {
                const __half2 h = __floats2half2_rn(
                    Wc1[(8 * k8 + 2 * t) * 128 + c],
                    Wc1[(8 * k8 + 2 * t + 1) * 128 + c]);
                hb[t] = *reinterpret_cast<const unsigned*>(&h);
            }
            ulonglong2 q;
            q.x = (u64)hb[0] | ((u64)hb[1] << 32);
            q.y = (u64)hb[2] | ((u64)hb[3] << 32);
            g_Wc1h[base] = q;
        }
    } else {                    // histogram role: batch-8 for MLP overlap
        const int t = (blockIdx.x - 64) * 256 + threadIdx.x;
        const int NT = NHB * 256;
        int dsts[8], cats[8];
        bool ok[8];
#pragma unroll
        for (int j = 0; j < 8; j++) {
            const int e = t + j * NT;
            ok[j] = e < 3 * EE;
            if (ok[j]) {
                cats[j] = e >= 2 * EE ? 2 : (e >= EE ? 1 : 0);
                const int le = e - cats[j] * EE;
                const int* ei = cats[j] == 0 ? e0 : (cats[j] == 1 ? e1 : e2);
                dsts[j] = __ldg(ei + EE + le);
            }
        }
#pragma unroll
        for (int j = 0; j < 8; j++)
            if (ok[j]) atomicAdd(&g_deg[cats[j]][dsts[j]], 1);
    }
}

// ---------------- k1: CSR scan -------------------------------------------------
__global__ void scan3_kernel()
{
    const int cat = blockIdx.x;
    const int* deg = g_deg[cat];
    int* rowptr = g_rowptr[cat];
    int* cur = g_cur[cat];
    const int t = threadIdx.x;              // 0..1023
    const int CH = (NN + 1023) / 1024;      // 40
    const int lo = t * CH;
    const int hi = min(lo + CH, NN);
    int s = 0;
    for (int i = lo; i < hi; i++) s += deg[i];
    __shared__ int wsum[32];
    const int lane = t & 31, wid = t >> 5;
    int v = s;
#pragma unroll
    for (int o = 1; o < 32; o <<= 1) {
        const int u = __shfl_up_sync(0xFFFFFFFFu, v, o);
        if (lane >= o) v += u;
    }
    if (lane == 31) wsum[wid] = v;
    __syncthreads();
    if (wid == 0) {
        int u = wsum[lane];
#pragma unroll
        for (int o = 1; o < 32; o <<= 1) {
            const int t2 = __shfl_up_sync(0xFFFFFFFFu, u, o);
            if (lane >= o) u += t2;
        }
        wsum[lane] = u;
    }
    __syncthreads();
    int run = v - s + (wid ? wsum[wid - 1] : 0);
    for (int i = lo; i < hi; i++) {
        rowptr[i] = run; cur[i] = run; run += deg[i];
    }
    if (t == 1023) rowptr[NN] = run;
}

// ------ GEMM body: xw = x @ W + fused attention dots (16 rows / tile) ---------
template <int DIN>
__device__ __forceinline__ void gemm_body(const float* __restrict__ x,
                                          const ulonglong2* __restrict__ Wq,
                                          const float* __restrict__ att_s,
                                          const float* __restrict__ att_d,
                                          __half* __restrict__ xw,
                                          float* __restrict__ as_,
                                          float* __restrict__ ad_,
                                          int r2, int stride, float* xs,
                                          float (*redbuf)[16][2])
{
    const int c = threadIdx.x;              // 0..127 output column
    const float vs = att_s[c];
    const float vd = att_d[c];
    const int w = c >> 5;
    for (int g = r2; g < NN / 16; g += stride) {
        const int n0 = g * 16;
        __syncthreads();
        for (int i = c; i < 16 * DIN / 4; i += 128)
            reinterpret_cast<float4*>(xs)[i] =
                reinterpret_cast<const float4*>(x + n0 * DIN)[i];
        __syncthreads();
        u64 acc2[16];
#pragma unroll
        for (int r = 0; r < 16; r++) acc2[r] = 0ull;
#pragma unroll 2
        for (int k4 = 0; k4 < DIN / 4; k4++) {
            const ulonglong2 wp = Wq[k4 * 128 + c];
#pragma unroll
            for (int r = 0; r < 16; r++) {
                const ulonglong2 a =
                    *reinterpret_cast<const ulonglong2*>(&xs[r * DIN + 4 * k4]);
                ffma2(acc2[r], a.x, wp.x);
                ffma2(acc2[r], a.y, wp.y);
            }
        }
#pragma unroll
        for (int r = 0; r < 16; r++) {
            const float accr = unpack_sum(acc2[r]);
            xw[(n0 + r) * HC + c] = __float2half_rn(accr);
            float ps = accr * vs, pd = accr * vd;
#pragma unroll
            for (int o = 16; o; o >>= 1) {
                ps += __shfl_down_sync(0xFFFFFFFFu, ps, o);
                pd += __shfl_down_sync(0xFFFFFFFFu, pd, o);
            }
            if ((c & 31) == 0) { redbuf[w][r][0] = ps; redbuf[w][r][1] = pd; }
        }
        __syncthreads();
        if (c < 32) {               // c encodes (r, h)
            const int r = c >> 1, h = c & 1;
            as_[(n0 + r) * 2 + h] = redbuf[2 * h][r][0] + redbuf[2 * h + 1][r][0];
            ad_[(n0 + r) * 2 + h] = redbuf[2 * h][r][1] + redbuf[2 * h + 1][r][1];
        }
    }
}

// ---------------- k2: 3 GEMMs + CSR scatter in one heterogeneous grid ---------
__global__ void __launch_bounds__(128)
phase1_kernel(const float* __restrict__ x0, const float* __restrict__ x1,
              const float* __restrict__ x2,
              const float* __restrict__ s0, const float* __restrict__ s1,
              const float* __restrict__ s2,
              const float* __restrict__ t0, const float* __restrict__ t1,
              const float* __restrict__ t2,
              const int* __restrict__ e0, const int* __restrict__ e1,
              const int* __restrict__ e2)
{
    __shared__ __align__(16) float xs[16 * 128];
    __shared__ float redbuf[4][16][2];
    const int role = blockIdx.x % ROLES;
    const int rank = blockIdx.x / ROLES;
    if (role < 4)
        gemm_body<128>(x0, g_Wq[0], s0, t0, g_xw[0], g_as[0], g_ad[0],
                       role * RPB + rank, 4 * RPB, xs, redbuf);
    else if (role < 8)
        gemm_body<128>(x1, g_Wq[1], s1, t1, g_xw[1], g_as[1], g_ad[1],
                       (role - 4) * RPB + rank, 4 * RPB, xs, redbuf);
    else if (role < 10)
        gemm_body<64>(x2, g_Wq[2], s2, t2, g_xw[2], g_as[2], g_ad[2],
                      (role - 8) * RPB + rank, 2 * RPB, xs, redbuf);
    else {                      // scatter role: build g_srt (independent of GEMM)
        const int stride = RPB * 128;
        for (int g = rank * 128 + threadIdx.x; g < 3 * EE; g += stride) {
            const int cat = g / EE, le = g - cat * EE;
            const int* ei = cat == 0 ? e0 : (cat == 1 ? e1 : e2);
            const int pos = atomicAdd(&g_cur[cat][ei[EE + le]], 1);
            g_srt[cat][pos] = ei[le];
        }
    }
}

// ---------------- k3: fused gather + softmax + ELU + MLP (16 nodes/block) -----
__global__ void __launch_bounds__(256, 5)
gather_mlp_kernel(const float* __restrict__ b0, const float* __restrict__ b1,
                  const float* __restrict__ b2,
                  const float* __restrict__ bc1, const float* __restrict__ Wc2,
                  const float* __restrict__ bc2, float* __restrict__ out)
{
    __shared__ __align__(16) float hs[16 * FUSED];
    __shared__ __align__(16) int4 recs[8][32];     // per-warp edge-record stage
    __shared__ float redm[8][8];
    const int tid = threadIdx.x, wid = tid >> 5, lane = tid & 31;
    const int n0 = blockIdx.x * 16;
    const int h = lane >> 4;                  // lanes 0-15 head0, 16-31 head1

    // -------- gather: each warp processes rows wid and wid+8 ------------------
    for (int cat = 0; cat < 3; cat++) {
        const float*  as_ = g_as[cat];
        const __half* xw  = g_xw[cat];
        const int*    srt = g_srt[cat];
        const float*  bias = cat == 0 ? b0 : (cat == 1 ? b1 : b2);

#pragma unroll
        for (int rep = 0; rep < 2; rep++) {
            const int row = wid + rep * 8;
            const int dst = n0 + row;

            const float2 ad2 = *reinterpret_cast<const float2*>(&g_ad[cat][dst * 2]);
            const float2 as2 = __ldg(reinterpret_cast<const float2*>(as_) + dst);
            float t0 = as2.x + ad2.x; t0 = t0 > 0.f ? t0 : 0.2f * t0;
            float t1 = as2.y + ad2.y; t1 = t1 > 0.f ? t1 : 0.2f * t1;
            const float exs0 = __expf(t0), exs1 = __expf(t1);
            float d0 = (lane == 0) ? exs0 : 0.f;
            float d1 = (lane == 0) ? exs1 : 0.f;
            const float exself = h ? exs1 : exs0;
            const uint2 sv = __ldg(reinterpret_cast<const uint2*>(
                                       xw + (size_t)dst * HC) + lane);
            float2 sa = __half22float2(*reinterpret_cast<const __half2*>(&sv.x));
            float2 sb = __half22float2(*reinterpret_cast<const __half2*>(&sv.y));
            float4 acc = make_float4(sa.x * exself, sa.y * exself,
                                     sb.x * exself, sb.y * exself);

            const int start = __ldg(&g_rowptr[cat][dst]);
            const int end   = __ldg(&g_rowptr[cat][dst + 1]);
            for (int p = start; p < end; p += 32) {
                const int n = min(32, end - p);
                const int mysrc = (lane < n) ? __ldg(srt + p + lane) : 0;
                const float2 a = __ldg(reinterpret_cast<const float2*>(as_) + mysrc);
                float u0 = a.x + ad2.x; u0 = u0 > 0.f ? u0 : 0.2f * u0;
                float u1 = a.y + ad2.y; u1 = u1 > 0.f ? u1 : 0.2f * u1;
                const float x0 = __expf(u0), x1 = __expf(u1);
                if (lane < n) { d0 += x0; d1 += x1; }
                recs[wid][lane] = make_int4(mysrc * HC, __float_as_int(x0),
                                            __float_as_int(x1), 0);
                __syncwarp();
#pragma unroll 4
                for (int i = 0; i < n; i++) {
                    const int4 rec = recs[wid][i];     // broadcast LDS
                    const float exh = h ? __int_as_float(rec.z)
                                        : __int_as_float(rec.y);
                    const uint2 uv = __ldg(reinterpret_cast<const uint2*>(
                                               xw + rec.x) + lane);
                    float2 fa = __half22float2(
                        *reinterpret_cast<const __half2*>(&uv.x));
                    float2 fb = __half22float2(
                        *reinterpret_cast<const __half2*>(&uv.y));
                    acc.x += fa.x * exh; acc.y += fa.y * exh;
                    acc.z += fb.x * exh; acc.w += fb.y * exh;
                }
                __syncwarp();
            }
#pragma unroll
            for (int o = 16; o; o >>= 1) {
                d0 += __shfl_xor_sync(0xFFFFFFFFu, d0, o);
                d1 += __shfl_xor_sync(0xFFFFFFFFu, d1, o);
            }
            const float inv = __fdividef(1.f, h ? d1 : d0);
            const int col = lane * 4;
            float4 o;
            o.x = acc.x * inv + bias[col + 0]; o.x = o.x > 0.f ? o.x : expm1f(o.x);
            o.y = acc.y * inv + bias[col + 1]; o.y = o.y > 0.f ? o.y : expm1f(o.y);
            o.z = acc.z * inv + bias[col + 2]; o.z = o.z > 0.f ? o.z : expm1f(o.z);
            o.w = acc.w * inv + bias[col + 3]; o.w = o.w > 0.f ? o.w : expm1f(o.w);
            *reinterpret_cast<float4*>(&hs[row * FUSED + cat * HC + col]) = o;
        }
    }
    __syncthreads();

    // ---- MLP: two 128-thread groups, full-K over own 8 rows, fp16 Wc1 --------
    const int j = tid & 127;           // hidden unit
    const int grp = tid >> 7;          // 0 -> rows 0-7, 1 -> rows 8-15
    u64 acc2[8];
#pragma unroll
    for (int r = 0; r < 8; r++) acc2[r] = 0ull;
#pragma unroll 2
    for (int k8 = 0; k8 < FUSED / 8; k8++) {
        const ulonglong2 wp = g_Wc1h[k8 * 128 + j];   // 8 fp16 k-values
        const u64 w01 = h2_to_u64f2((unsigned)(wp.x));
        const u64 w23 = h2_to_u64f2((unsigned)(wp.x >> 32));
        const u64 w45 = h2_to_u64f2((unsigned)(wp.y));
        const u64 w67 = h2_to_u64f2((unsigned)(wp.y >> 32));
#pragma unroll
        for (int r = 0; r < 8; r++) {
            const float* hrow = &hs[(grp * 8 + r) * FUSED + 8 * k8];
            const ulonglong2 a0 = *reinterpret_cast<const ulonglong2*>(hrow);
            const ulonglong2 a1 = *reinterpret_cast<const ulonglong2*>(hrow + 4);
            ffma2(acc2[r], a0.x, w01);
            ffma2(acc2[r], a0.y, w23);
            ffma2(acc2[r], a1.x, w45);
            ffma2(acc2[r], a1.y, w67);
        }
    }
    const float w2c = Wc2[j];
    const float b1c = bc1[j];
#pragma unroll
    for (int r = 0; r < 8; r++) {
        float hv = unpack_sum(acc2[r]) + b1c;
        hv = fmaxf(hv, 0.f);
        float p = hv * w2c;
#pragma unroll
        for (int o = 16; o; o >>= 1) p += __shfl_down_sync(0xFFFFFFFFu, p, o);
        if (lane == 0) redm[wid][r] = p;   // wid 0-3: rows 0-7; wid 4-7: rows 8-15
    }
    __syncthreads();
    if (tid < 16) {
        const int grp2 = tid >> 3;         // which group owns this row
        const int r = tid & 7;
        const int wbase = grp2 * 4;
        out[n0 + tid] = redm[wbase + 0][r] + redm[wbase + 1][r] +
                        redm[wbase + 2][r] + redm[wbase + 3][r] + bc2[0];
    }
}

// ---------------- host orchestration ------------------------------------------
extern "C" void kernel_launch(void* const* d_in, const int* in_sizes, int n_in,
                              void* d_out, int out_size)
{
    const float* x[3];  const int* ei[3];  const float* W[3];
    const float* atts[3]; const float* attd[3]; const float* bias[3];
    for (int i = 0; i < 3; i++) {
        x[i]    = (const float*)d_in[6 * i + 0];
        ei[i]   = (const int*)  d_in[6 * i + 1];
        W[i]    = (const float*)d_in[6 * i + 2];
        atts[i] = (const float*)d_in[6 * i + 3];
        attd[i] = (const float*)d_in[6 * i + 4];
        bias[i] = (const float*)d_in[6 * i + 5];
    }
    const float* Wc1 = (const float*)d_in[18];
    const float* bc1 = (const float*)d_in[19];
    const float* Wc2 = (const float*)d_in[20];
    const float* bc2 = (const float*)d_in[21];
    float* out = (float*)d_out;

    int* p_deg;
    cudaGetSymbolAddress((void**)&p_deg, g_deg);
    cudaMemsetAsync(p_deg, 0, sizeof(int) * 3 * NN);

    // k0: pack+hist   k1: scan   k2: phase1   k3: gather_mlp (capture slot)
    pack_hist_kernel<<<64 + NHB, 256>>>(
        W[0], W[1], W[2], Wc1, ei[0], ei[1], ei[2]);

    scan3_kernel<<<3, 1024>>>();

    phase1_kernel<<<P1GRID, 128>>>(x[0], x[1], x[2],
                                   atts[0], atts[1], atts[2],
                                   attd[0], attd[1], attd[2],
                                   ei[0], ei[1], ei[2]);

    gather_mlp_kernel<<<NN / 16, 256>>>(bias[0], bias[1], bias[2],
                                        bc1, Wc2, bc2, out);
}